// round 9
// baseline (speedup 1.0000x reference)
#include <cuda_runtime.h>

#define BATCH 64
#define SEQ   512
#define HID   1024
#define LBL   5
#define ESTR  8    // padded row stride (floats) for emissions / v-history

// Scratch (no allocations allowed -> __device__ globals)
__device__ float g_emis[BATCH * SEQ * ESTR];  // relu(feats@W+b), [B,S,8(5 used)]
__device__ float g_res[BATCH];                // per-batch (numerator - log_z)
__device__ int   g_cnt = 0;                   // last-block election counter

// nibble-packed tag maps: bits [4q,4q+3) = f(q), q in 0..4. identity = 0x43210.
__device__ __forceinline__ unsigned compose_map(unsigned f, unsigned g) {
    // (f o g)(x) = f(g(x))
    unsigned r = 0;
#pragma unroll
    for (int q = 0; q < 5; q++) {
        unsigned gq = (g >> (4 * q)) & 7u;
        r |= ((f >> (gq * 4)) & 7u) << (4 * q);
    }
    return r;
}
__device__ __forceinline__ int apply_map(unsigned m, int x) {
    return (int)((m >> (x * 4)) & 7u);
}

// ---------------------------------------------------------------------------
// Kernel 1: emissions = relu(feats @ W_tag + b_tag)
// 8 rows per warp, 256-thread blocks (R5 version - best measured emis).
// ---------------------------------------------------------------------------
__global__ __launch_bounds__(256) void emis_kernel(
    const float* __restrict__ feats,   // [B*S, HID]
    const float* __restrict__ W,       // [HID, LBL]
    const float* __restrict__ bias)    // [LBL]
{
    __shared__ float sW[LBL * HID];    // transposed: sW[j*HID + k]
    int tid = threadIdx.x;
    for (int idx = tid; idx < LBL * HID; idx += 256) {
        int k = idx / LBL, j = idx - k * LBL;
        sW[j * HID + k] = W[idx];
    }
    __syncthreads();

    int warp = tid >> 5, lane = tid & 31;
    int row0 = blockIdx.x * 64 + warp * 8;   // 8 warps * 8 rows = 64 rows/block

    const float4* w4 = reinterpret_cast<const float4*>(sW);
    const float4* f4 = reinterpret_cast<const float4*>(feats) + (size_t)row0 * (HID / 4);

    float acc[8][LBL];
#pragma unroll
    for (int r = 0; r < 8; r++)
#pragma unroll
        for (int j = 0; j < LBL; j++) acc[r][j] = 0.f;

#pragma unroll
    for (int i = 0; i < HID / 4 / 32; i++) {
        int k4 = lane + 32 * i;
        float4 f[8];
#pragma unroll
        for (int r = 0; r < 8; r++) f[r] = f4[(size_t)r * (HID / 4) + k4];
#pragma unroll
        for (int j = 0; j < LBL; j++) {
            float4 w = w4[j * (HID / 4) + k4];
#pragma unroll
            for (int r = 0; r < 8; r++)
                acc[r][j] += f[r].x * w.x + f[r].y * w.y + f[r].z * w.z + f[r].w * w.w;
        }
    }

#pragma unroll
    for (int r = 0; r < 8; r++)
#pragma unroll
        for (int j = 0; j < LBL; j++)
#pragma unroll
            for (int off = 16; off; off >>= 1)
                acc[r][j] += __shfl_down_sync(0xffffffffu, acc[r][j], off);

    if (lane == 0) {
#pragma unroll
        for (int r = 0; r < 8; r++) {
            float* o = g_emis + (size_t)(row0 + r) * ESTR;
            float v[LBL];
#pragma unroll
            for (int j = 0; j < LBL; j++)
                v[j] = fmaxf(acc[r][j] + bias[j], 0.f);
            *reinterpret_cast<float4*>(o) = make_float4(v[0], v[1], v[2], v[3]);
            o[4] = v[4];
        }
    }
}

// ---------------------------------------------------------------------------
// Kernel 2: per-batch CRF. One block per batch, 10 warps:
//   warp 9   : shuffle-free sequential Viterbi (replicated registers).
//              Per-step v-history store = PREDICATED PTX STS (no BSSY/BSYNC
//              branch machinery in the 511-step hot loop).
//   warp 0   : gold-path numerator
//   warps 1-8: forward logsumexp chunk operators; warp 1 composes -> log_z
// Join, then: parallel bp recompute into nibble-packed maps, single-warp
// suffix-scan backtrace (exact), path write, warp-parallel loss finalize.
// ---------------------------------------------------------------------------
__global__ __launch_bounds__(320) void crf_kernel(
    const int*   __restrict__ labels,       // [B, S]
    const float* __restrict__ start_trans,  // [L]
    const float* __restrict__ end_trans,    // [L]
    const float* __restrict__ trans,        // [L, L] (prev, cur)
    const float* __restrict__ weights,      // [L]
    float*       __restrict__ d_out)        // [0]=loss, [1..]=paths
{
    __shared__ __align__(16) float s_e[SEQ * ESTR];  // emissions (stride 8)
    __shared__ __align__(16) float s_v[SEQ * ESTR];  // viterbi value history
    __shared__ unsigned      s_F[SEQ];               // nibble-packed bp maps
    __shared__ unsigned char s_path[SEQ];
    __shared__ float         s_M[8][25];             // forward chunk operators
    __shared__ float         s_T[25];                // trans staged
    __shared__ float         s_logz, s_num;
    __shared__ int           s_last, s_islast;

    int b = blockIdx.x;
    int tid = threadIdx.x, warp = tid >> 5, lane = tid & 31;

    // Stage emissions (16KB, vectorized) + trans
    {
        const uint4* gsrc = reinterpret_cast<const uint4*>(g_emis + (size_t)b * SEQ * ESTR);
        uint4* sdst = reinterpret_cast<uint4*>(s_e);
        for (int i = tid; i < SEQ * ESTR / 4; i += 320) sdst[i] = gsrc[i];
        if (tid < 25) s_T[tid] = trans[tid];
    }
    __syncthreads();

    if (warp == 9) {
        // ---------------- Viterbi: replicated registers, no shuffles -------
        float T[LBL][LBL];
#pragma unroll
        for (int i = 0; i < LBL; i++)
#pragma unroll
            for (int j = 0; j < LBL; j++) T[i][j] = s_T[i * LBL + j];

        // smem byte address of s_v for predicated stores
        unsigned sv_addr;
        asm("{ .reg .u64 t; cvta.to.shared.u64 t, %1; cvt.u32.u64 %0, t; }"
            : "=r"(sv_addr) : "l"(&s_v[0]));
        unsigned p32 = (lane == 0) ? 1u : 0u;   // store predicate

        float v0 = start_trans[0] + s_e[0];
        float v1 = start_trans[1] + s_e[1];
        float v2 = start_trans[2] + s_e[2];
        float v3 = start_trans[3] + s_e[3];
        float v4 = start_trans[4] + s_e[4];
        asm volatile(
            "{ .reg .pred p; setp.ne.u32 p, %0, 0;\n\t"
            "@p st.shared.v4.f32 [%1], {%2,%3,%4,%5};\n\t"
            "@p st.shared.f32 [%1+16], %6; }"
            :: "r"(p32), "r"(sv_addr), "f"(v0), "f"(v1), "f"(v2), "f"(v3), "f"(v4));

#pragma unroll 4
        for (int t = 1; t < SEQ; t++) {
            float4 ea = *reinterpret_cast<const float4*>(&s_e[t * ESTR]);
            float  e4 = s_e[t * ESTR + 4];

            float n0 = fmaxf(fmaxf(fmaxf(v0 + T[0][0], v1 + T[1][0]),
                                   fmaxf(v2 + T[2][0], v3 + T[3][0])), v4 + T[4][0]) + ea.x;
            float n1 = fmaxf(fmaxf(fmaxf(v0 + T[0][1], v1 + T[1][1]),
                                   fmaxf(v2 + T[2][1], v3 + T[3][1])), v4 + T[4][1]) + ea.y;
            float n2 = fmaxf(fmaxf(fmaxf(v0 + T[0][2], v1 + T[1][2]),
                                   fmaxf(v2 + T[2][2], v3 + T[3][2])), v4 + T[4][2]) + ea.z;
            float n3 = fmaxf(fmaxf(fmaxf(v0 + T[0][3], v1 + T[1][3]),
                                   fmaxf(v2 + T[2][3], v3 + T[3][3])), v4 + T[4][3]) + ea.w;
            float n4 = fmaxf(fmaxf(fmaxf(v0 + T[0][4], v1 + T[1][4]),
                                   fmaxf(v2 + T[2][4], v3 + T[3][4])), v4 + T[4][4]) + e4;
            v0 = n0; v1 = n1; v2 = n2; v3 = n3; v4 = n4;

            // branch-free predicated v-history store (no BSSY/BSYNC)
            unsigned a = sv_addr + (unsigned)(t * ESTR * 4);
            asm volatile(
                "{ .reg .pred p; setp.ne.u32 p, %0, 0;\n\t"
                "@p st.shared.v4.f32 [%1], {%2,%3,%4,%5};\n\t"
                "@p st.shared.f32 [%1+16], %6; }"
                :: "r"(p32), "r"(a), "f"(v0), "f"(v1), "f"(v2), "f"(v3), "f"(v4));
        }

        // last = argmax(v + end), first index wins ties (replicated, exact)
        float f0 = v0 + end_trans[0];
        float f1 = v1 + end_trans[1];
        float f2 = v2 + end_trans[2];
        float f3 = v3 + end_trans[3];
        float f4 = v4 + end_trans[4];
        float fb = f0; int last = 0;
        if (f1 > fb) { fb = f1; last = 1; }
        if (f2 > fb) { fb = f2; last = 2; }
        if (f3 > fb) { fb = f3; last = 3; }
        if (f4 > fb) { fb = f4; last = 4; }
        if (lane == 0) s_last = last;
    } else if (warp == 0) {
        // ---------------- numerator ----------------
        const int* lb = labels + b * SEQ;
        float acc = 0.f;
        for (int t = lane; t < SEQ; t += 32) {
            int l = lb[t];
            acc += weights[l] * s_e[t * ESTR + l];
            if (t + 1 < SEQ) acc += trans[l * LBL + lb[t + 1]];
        }
#pragma unroll
        for (int off = 16; off; off >>= 1)
            acc += __shfl_down_sync(0xffffffffu, acc, off);
        if (lane == 0)
            s_num = acc + start_trans[lb[0]] + end_trans[lb[SEQ - 1]];
    } else {
        // ---------------- forward chunks (warps 1..8, chunk c = warp-1) ----
        int c = warp - 1;
        int t0 = (c == 0) ? 1 : 64 * c;
        int t1 = 64 * c + 63;
        bool act = lane < 25;
        int p = act ? lane : 0;
        int i5 = (p / 5) * 5;       // base lane of my source row
        int jj = p % 5;

        float Tr0 = s_T[0 * LBL + jj];
        float Tr1 = s_T[1 * LBL + jj];
        float Tr2 = s_T[2 * LBL + jj];
        float Tr3 = s_T[3 * LBL + jj];
        float Tr4 = s_T[4 * LBL + jj];

        // M = A_{t0}
        float M = s_T[(p / 5) * LBL + jj] + s_e[t0 * ESTR + jj];

        for (int t = t0 + 1; t <= t1; t++) {
            float e = s_e[t * ESTR + jj];
            float m0 = __shfl_sync(0xffffffffu, M, i5 + 0);
            float m1 = __shfl_sync(0xffffffffu, M, i5 + 1);
            float m2 = __shfl_sync(0xffffffffu, M, i5 + 2);
            float m3 = __shfl_sync(0xffffffffu, M, i5 + 3);
            float m4 = __shfl_sync(0xffffffffu, M, i5 + 4);
            float x0 = m0 + Tr0, x1 = m1 + Tr1, x2 = m2 + Tr2,
                  x3 = m3 + Tr3, x4 = m4 + Tr4;
            float mm = fmaxf(fmaxf(fmaxf(x0, x1), fmaxf(x2, x3)), x4);
            float me = mm + e;
            float s = (__expf(x0 - mm) + __expf(x1 - mm))
                    + (__expf(x2 - mm) + __expf(x3 - mm)) + __expf(x4 - mm);
            M = me + __logf(s);
        }
        if (act) s_M[c][p] = M;

        asm volatile("bar.sync 1, 256;" ::: "memory");  // warps 1..8 only

        if (warp == 1) {
            // compose: alpha0 (x) M_0 (x) ... (x) M_7, then log_z
            int j = (lane < LBL) ? lane : 0;
            float al = start_trans[j] + s_e[j];
#pragma unroll
            for (int cc = 0; cc < 8; cc++) {
                float a0 = __shfl_sync(0xffffffffu, al, 0);
                float a1 = __shfl_sync(0xffffffffu, al, 1);
                float a2 = __shfl_sync(0xffffffffu, al, 2);
                float a3 = __shfl_sync(0xffffffffu, al, 3);
                float a4 = __shfl_sync(0xffffffffu, al, 4);
                float x0 = a0 + s_M[cc][0 * 5 + j];
                float x1 = a1 + s_M[cc][1 * 5 + j];
                float x2 = a2 + s_M[cc][2 * 5 + j];
                float x3 = a3 + s_M[cc][3 * 5 + j];
                float x4 = a4 + s_M[cc][4 * 5 + j];
                float mm = fmaxf(fmaxf(fmaxf(x0, x1), fmaxf(x2, x3)), x4);
                float s = (__expf(x0 - mm) + __expf(x1 - mm))
                        + (__expf(x2 - mm) + __expf(x3 - mm)) + __expf(x4 - mm);
                al = mm + __logf(s);
            }
            float z = al + end_trans[j];
            float z0 = __shfl_sync(0xffffffffu, z, 0);
            float z1 = __shfl_sync(0xffffffffu, z, 1);
            float z2 = __shfl_sync(0xffffffffu, z, 2);
            float z3 = __shfl_sync(0xffffffffu, z, 3);
            float z4 = __shfl_sync(0xffffffffu, z, 4);
            float mz = fmaxf(fmaxf(fmaxf(z0, z1), fmaxf(z2, z3)), z4);
            float sz = __expf(z0 - mz) + __expf(z1 - mz) + __expf(z2 - mz)
                     + __expf(z3 - mz) + __expf(z4 - mz);
            if (lane == 0) s_logz = mz + __logf(sz);
        }
    }
    __syncthreads();

    // per-batch result; elect last block (loss reduced warp-parallel below)
    if (tid == 0) {
        g_res[b] = s_num - s_logz;
        __threadfence();
        int done = atomicAdd(&g_cnt, 1);
        s_islast = (done == BATCH - 1) ? 1 : 0;
    }

    // ------- parallel bp recompute into nibble-packed maps (exact) -------
    {
        float Tl[25];
#pragma unroll
        for (int q = 0; q < 25; q++) Tl[q] = s_T[q];
        for (int t = tid; t < SEQ; t += 320) {
            if (t < SEQ - 1) {
                float4 va = *reinterpret_cast<const float4*>(&s_v[t * ESTR]);
                float  vb = s_v[t * ESTR + 4];
                unsigned m = 0;
#pragma unroll
                for (int j = 0; j < LBL; j++) {
                    float y0 = va.x + Tl[0 * LBL + j];
                    float y1 = va.y + Tl[1 * LBL + j];
                    float y2 = va.z + Tl[2 * LBL + j];
                    float y3 = va.w + Tl[3 * LBL + j];
                    float y4 = vb   + Tl[4 * LBL + j];
                    float best = y0; unsigned idx = 0;
                    if (y1 > best) { best = y1; idx = 1; }
                    if (y2 > best) { best = y2; idx = 2; }
                    if (y3 > best) { best = y3; idx = 3; }
                    if (y4 > best) { best = y4; idx = 4; }
                    m |= idx << (4 * j);
                }
                s_F[t] = m;
            } else {
                s_F[t] = 0x43210u;   // identity map at t = SEQ-1
            }
        }
    }
    __syncthreads();

    // ------- single-warp suffix-scan backtrace (exact integer maps) -------
    if (warp == 0) {
        // lane l owns t in [16l, 16l+16)
        unsigned m[16];
#pragma unroll
        for (int k = 0; k < 16; k++) m[k] = s_F[16 * lane + k];

        // chunk product C = m[0] o m[1] o ... o m[15]
        unsigned C = m[15];
#pragma unroll
        for (int k = 14; k >= 0; k--) C = compose_map(m[k], C);

        // Kogge-Stone inclusive suffix scan over lanes
#pragma unroll
        for (int d = 1; d < 32; d <<= 1) {
            unsigned o = __shfl_down_sync(0xffffffffu, C, d);
            if (lane + d < 32) C = compose_map(C, o);
        }
        // entry tag for this lane = Sigma_{l+1}(last)
        unsigned Snext = __shfl_down_sync(0xffffffffu, C, 1);
        if (lane == 31) Snext = 0x43210u;
        int x = apply_map(Snext, s_last);
#pragma unroll
        for (int k = 15; k >= 0; k--) {
            x = apply_map(m[k], x);
            s_path[16 * lane + k] = (unsigned char)x;
        }
    } else if (warp == 1) {
        // warp-parallel deterministic loss reduction (last block only)
        if (s_islast) {
            float a = g_res[lane] + g_res[lane + 32];
#pragma unroll
            for (int off = 16; off; off >>= 1)
                a += __shfl_down_sync(0xffffffffu, a, off);
            if (lane == 0) {
                d_out[0] = -a / (float)(BATCH * SEQ);
                g_cnt = 0;  // reset for next graph replay
            }
        }
    }
    __syncthreads();

    // write decoded paths (float, coalesced)
    float* out_paths = d_out + 1;
    for (int t = tid; t < SEQ; t += 320)
        out_paths[(size_t)b * SEQ + t] = (float)s_path[t];
}

// ---------------------------------------------------------------------------
extern "C" void kernel_launch(void* const* d_in, const int* in_sizes, int n_in,
                              void* d_out, int out_size)
{
    const float* feats       = (const float*)d_in[0];  // [B,S,H]
    const int*   labels      = (const int*)  d_in[1];  // [B,S]
    // d_in[2] = mask: all-ones by construction, ignored
    const float* W_tag       = (const float*)d_in[3];  // [H,L]
    const float* b_tag       = (const float*)d_in[4];  // [L]
    const float* start_trans = (const float*)d_in[5];  // [L]
    const float* end_trans   = (const float*)d_in[6];  // [L]
    const float* trans       = (const float*)d_in[7];  // [L,L]
    const float* weights     = (const float*)d_in[8];  // [L]

    float* out = (float*)d_out;  // [0] = loss, [1..B*S] = paths

    emis_kernel<<<(BATCH * SEQ) / 64, 256>>>(feats, W_tag, b_tag);
    crf_kernel<<<BATCH, 320>>>(labels, start_trans, end_trans, trans, weights, out);
}

// round 10
// speedup vs baseline: 1.6945x; 1.6945x over previous
#include <cuda_runtime.h>

#define BATCH 64
#define SEQ   512
#define HID   1024
#define LBL   5
#define ESTR  8    // padded row stride (floats) for emissions / v-history

// Scratch (no allocations allowed -> __device__ globals)
__device__ float g_emis[BATCH * SEQ * ESTR];  // relu(feats@W+b), [B,S,8(5 used)]
__device__ float g_res[BATCH];                // per-batch (numerator - log_z)
__device__ int   g_cnt = 0;                   // last-block election counter

// nibble-packed tag maps: bits [4q,4q+3) = f(q), q in 0..4. identity = 0x43210.
__device__ __forceinline__ unsigned compose_map(unsigned f, unsigned g) {
    // (f o g)(x) = f(g(x))
    unsigned r = 0;
#pragma unroll
    for (int q = 0; q < 5; q++) {
        unsigned gq = (g >> (4 * q)) & 7u;
        r |= ((f >> (gq * 4)) & 7u) << (4 * q);
    }
    return r;
}
__device__ __forceinline__ int apply_map(unsigned m, int x) {
    return (int)((m >> (x * 4)) & 7u);
}

// ---------------------------------------------------------------------------
// Kernel 1: emissions = relu(feats @ W_tag + b_tag)
// 8 rows per warp, 256-thread blocks (best measured emis variant).
// ---------------------------------------------------------------------------
__global__ __launch_bounds__(256) void emis_kernel(
    const float* __restrict__ feats,   // [B*S, HID]
    const float* __restrict__ W,       // [HID, LBL]
    const float* __restrict__ bias)    // [LBL]
{
    __shared__ float sW[LBL * HID];    // transposed: sW[j*HID + k]
    int tid = threadIdx.x;
    for (int idx = tid; idx < LBL * HID; idx += 256) {
        int k = idx / LBL, j = idx - k * LBL;
        sW[j * HID + k] = W[idx];
    }
    __syncthreads();

    int warp = tid >> 5, lane = tid & 31;
    int row0 = blockIdx.x * 64 + warp * 8;   // 8 warps * 8 rows = 64 rows/block

    const float4* w4 = reinterpret_cast<const float4*>(sW);
    const float4* f4 = reinterpret_cast<const float4*>(feats) + (size_t)row0 * (HID / 4);

    float acc[8][LBL];
#pragma unroll
    for (int r = 0; r < 8; r++)
#pragma unroll
        for (int j = 0; j < LBL; j++) acc[r][j] = 0.f;

#pragma unroll
    for (int i = 0; i < HID / 4 / 32; i++) {
        int k4 = lane + 32 * i;
        float4 f[8];
#pragma unroll
        for (int r = 0; r < 8; r++) f[r] = f4[(size_t)r * (HID / 4) + k4];
#pragma unroll
        for (int j = 0; j < LBL; j++) {
            float4 w = w4[j * (HID / 4) + k4];
#pragma unroll
            for (int r = 0; r < 8; r++)
                acc[r][j] += f[r].x * w.x + f[r].y * w.y + f[r].z * w.z + f[r].w * w.w;
        }
    }

#pragma unroll
    for (int r = 0; r < 8; r++)
#pragma unroll
        for (int j = 0; j < LBL; j++)
#pragma unroll
            for (int off = 16; off; off >>= 1)
                acc[r][j] += __shfl_down_sync(0xffffffffu, acc[r][j], off);

    if (lane == 0) {
#pragma unroll
        for (int r = 0; r < 8; r++) {
            float* o = g_emis + (size_t)(row0 + r) * ESTR;
            float v[LBL];
#pragma unroll
            for (int j = 0; j < LBL; j++)
                v[j] = fmaxf(acc[r][j] + bias[j], 0.f);
            *reinterpret_cast<float4*>(o) = make_float4(v[0], v[1], v[2], v[3]);
            o[4] = v[4];
        }
    }
}

// ---------------------------------------------------------------------------
// Kernel 2: per-batch CRF. One block per batch, 10 warps:
//   warp 9   : shuffle-free sequential Viterbi (states replicated in ALL
//              lanes). v-history store is UNCONDITIONAL: every lane stores
//              the identical value to the same smem address (same-address
//              same-value STS = single commit, no conflict, NO branch
//              machinery, no asm fences -> ptxas pipelines freely).
//   warp 0   : gold-path numerator
//   warps 1-8: forward logsumexp chunk operators; warp 1 composes -> log_z
// Join, then: parallel bp recompute into nibble-packed maps, single-warp
// suffix-scan backtrace (exact), path write, warp-parallel loss finalize.
// ---------------------------------------------------------------------------
__global__ __launch_bounds__(320) void crf_kernel(
    const int*   __restrict__ labels,       // [B, S]
    const float* __restrict__ start_trans,  // [L]
    const float* __restrict__ end_trans,    // [L]
    const float* __restrict__ trans,        // [L, L] (prev, cur)
    const float* __restrict__ weights,      // [L]
    float*       __restrict__ d_out)        // [0]=loss, [1..]=paths
{
    __shared__ __align__(16) float s_e[SEQ * ESTR];  // emissions (stride 8)
    __shared__ __align__(16) float s_v[SEQ * ESTR];  // viterbi value history
    __shared__ unsigned      s_F[SEQ];               // nibble-packed bp maps
    __shared__ unsigned char s_path[SEQ];
    __shared__ float         s_M[8][25];             // forward chunk operators
    __shared__ float         s_T[25];                // trans staged
    __shared__ float         s_logz, s_num;
    __shared__ int           s_last, s_islast;

    int b = blockIdx.x;
    int tid = threadIdx.x, warp = tid >> 5, lane = tid & 31;

    // Stage emissions (16KB, vectorized) + trans
    {
        const uint4* gsrc = reinterpret_cast<const uint4*>(g_emis + (size_t)b * SEQ * ESTR);
        uint4* sdst = reinterpret_cast<uint4*>(s_e);
        for (int i = tid; i < SEQ * ESTR / 4; i += 320) sdst[i] = gsrc[i];
        if (tid < 25) s_T[tid] = trans[tid];
    }
    __syncthreads();

    if (warp == 9) {
        // ---------------- Viterbi: replicated registers, no shuffles -------
        float T[LBL][LBL];
#pragma unroll
        for (int i = 0; i < LBL; i++)
#pragma unroll
            for (int j = 0; j < LBL; j++) T[i][j] = s_T[i * LBL + j];

        float v0 = start_trans[0] + s_e[0];
        float v1 = start_trans[1] + s_e[1];
        float v2 = start_trans[2] + s_e[2];
        float v3 = start_trans[3] + s_e[3];
        float v4 = start_trans[4] + s_e[4];
        // all lanes store identical values to the same address: conflict-free
        *reinterpret_cast<float4*>(&s_v[0]) = make_float4(v0, v1, v2, v3);
        s_v[4] = v4;

#pragma unroll 2
        for (int t = 1; t < SEQ; t++) {
            float4 ea = *reinterpret_cast<const float4*>(&s_e[t * ESTR]);
            float  e4 = s_e[t * ESTR + 4];

            float n0 = fmaxf(fmaxf(fmaxf(v0 + T[0][0], v1 + T[1][0]),
                                   fmaxf(v2 + T[2][0], v3 + T[3][0])), v4 + T[4][0]) + ea.x;
            float n1 = fmaxf(fmaxf(fmaxf(v0 + T[0][1], v1 + T[1][1]),
                                   fmaxf(v2 + T[2][1], v3 + T[3][1])), v4 + T[4][1]) + ea.y;
            float n2 = fmaxf(fmaxf(fmaxf(v0 + T[0][2], v1 + T[1][2]),
                                   fmaxf(v2 + T[2][2], v3 + T[3][2])), v4 + T[4][2]) + ea.z;
            float n3 = fmaxf(fmaxf(fmaxf(v0 + T[0][3], v1 + T[1][3]),
                                   fmaxf(v2 + T[2][3], v3 + T[3][3])), v4 + T[4][3]) + ea.w;
            float n4 = fmaxf(fmaxf(fmaxf(v0 + T[0][4], v1 + T[1][4]),
                                   fmaxf(v2 + T[2][4], v3 + T[3][4])), v4 + T[4][4]) + e4;
            v0 = n0; v1 = n1; v2 = n2; v3 = n3; v4 = n4;

            // unconditional all-lane store (same addr, same value)
            *reinterpret_cast<float4*>(&s_v[t * ESTR]) = make_float4(v0, v1, v2, v3);
            s_v[t * ESTR + 4] = v4;
        }

        // last = argmax(v + end), first index wins ties (replicated, exact)
        float f0 = v0 + end_trans[0];
        float f1 = v1 + end_trans[1];
        float f2 = v2 + end_trans[2];
        float f3 = v3 + end_trans[3];
        float f4 = v4 + end_trans[4];
        float fb = f0; int last = 0;
        if (f1 > fb) { fb = f1; last = 1; }
        if (f2 > fb) { fb = f2; last = 2; }
        if (f3 > fb) { fb = f3; last = 3; }
        if (f4 > fb) { fb = f4; last = 4; }
        if (lane == 0) s_last = last;
    } else if (warp == 0) {
        // ---------------- numerator ----------------
        const int* lb = labels + b * SEQ;
        float acc = 0.f;
        for (int t = lane; t < SEQ; t += 32) {
            int l = lb[t];
            acc += weights[l] * s_e[t * ESTR + l];
            if (t + 1 < SEQ) acc += trans[l * LBL + lb[t + 1]];
        }
#pragma unroll
        for (int off = 16; off; off >>= 1)
            acc += __shfl_down_sync(0xffffffffu, acc, off);
        if (lane == 0)
            s_num = acc + start_trans[lb[0]] + end_trans[lb[SEQ - 1]];
    } else {
        // ---------------- forward chunks (warps 1..8, chunk c = warp-1) ----
        int c = warp - 1;
        int t0 = (c == 0) ? 1 : 64 * c;
        int t1 = 64 * c + 63;
        bool act = lane < 25;
        int p = act ? lane : 0;
        int i5 = (p / 5) * 5;       // base lane of my source row
        int jj = p % 5;

        float Tr0 = s_T[0 * LBL + jj];
        float Tr1 = s_T[1 * LBL + jj];
        float Tr2 = s_T[2 * LBL + jj];
        float Tr3 = s_T[3 * LBL + jj];
        float Tr4 = s_T[4 * LBL + jj];

        // M = A_{t0}
        float M = s_T[(p / 5) * LBL + jj] + s_e[t0 * ESTR + jj];

        for (int t = t0 + 1; t <= t1; t++) {
            float e = s_e[t * ESTR + jj];
            float m0 = __shfl_sync(0xffffffffu, M, i5 + 0);
            float m1 = __shfl_sync(0xffffffffu, M, i5 + 1);
            float m2 = __shfl_sync(0xffffffffu, M, i5 + 2);
            float m3 = __shfl_sync(0xffffffffu, M, i5 + 3);
            float m4 = __shfl_sync(0xffffffffu, M, i5 + 4);
            float x0 = m0 + Tr0, x1 = m1 + Tr1, x2 = m2 + Tr2,
                  x3 = m3 + Tr3, x4 = m4 + Tr4;
            float mm = fmaxf(fmaxf(fmaxf(x0, x1), fmaxf(x2, x3)), x4);
            float me = mm + e;
            float s = (__expf(x0 - mm) + __expf(x1 - mm))
                    + (__expf(x2 - mm) + __expf(x3 - mm)) + __expf(x4 - mm);
            M = me + __logf(s);
        }
        if (act) s_M[c][p] = M;

        asm volatile("bar.sync 1, 256;" ::: "memory");  // warps 1..8 only

        if (warp == 1) {
            // compose: alpha0 (x) M_0 (x) ... (x) M_7, then log_z
            int j = (lane < LBL) ? lane : 0;
            float al = start_trans[j] + s_e[j];
#pragma unroll
            for (int cc = 0; cc < 8; cc++) {
                float a0 = __shfl_sync(0xffffffffu, al, 0);
                float a1 = __shfl_sync(0xffffffffu, al, 1);
                float a2 = __shfl_sync(0xffffffffu, al, 2);
                float a3 = __shfl_sync(0xffffffffu, al, 3);
                float a4 = __shfl_sync(0xffffffffu, al, 4);
                float x0 = a0 + s_M[cc][0 * 5 + j];
                float x1 = a1 + s_M[cc][1 * 5 + j];
                float x2 = a2 + s_M[cc][2 * 5 + j];
                float x3 = a3 + s_M[cc][3 * 5 + j];
                float x4 = a4 + s_M[cc][4 * 5 + j];
                float mm = fmaxf(fmaxf(fmaxf(x0, x1), fmaxf(x2, x3)), x4);
                float s = (__expf(x0 - mm) + __expf(x1 - mm))
                        + (__expf(x2 - mm) + __expf(x3 - mm)) + __expf(x4 - mm);
                al = mm + __logf(s);
            }
            float z = al + end_trans[j];
            float z0 = __shfl_sync(0xffffffffu, z, 0);
            float z1 = __shfl_sync(0xffffffffu, z, 1);
            float z2 = __shfl_sync(0xffffffffu, z, 2);
            float z3 = __shfl_sync(0xffffffffu, z, 3);
            float z4 = __shfl_sync(0xffffffffu, z, 4);
            float mz = fmaxf(fmaxf(fmaxf(z0, z1), fmaxf(z2, z3)), z4);
            float sz = __expf(z0 - mz) + __expf(z1 - mz) + __expf(z2 - mz)
                     + __expf(z3 - mz) + __expf(z4 - mz);
            if (lane == 0) s_logz = mz + __logf(sz);
        }
    }
    __syncthreads();

    // per-batch result; elect last block (loss reduced warp-parallel below)
    if (tid == 0) {
        g_res[b] = s_num - s_logz;
        __threadfence();
        int done = atomicAdd(&g_cnt, 1);
        s_islast = (done == BATCH - 1) ? 1 : 0;
    }

    // ------- parallel bp recompute into nibble-packed maps (exact) -------
    {
        float Tl[25];
#pragma unroll
        for (int q = 0; q < 25; q++) Tl[q] = s_T[q];
        for (int t = tid; t < SEQ; t += 320) {
            if (t < SEQ - 1) {
                float4 va = *reinterpret_cast<const float4*>(&s_v[t * ESTR]);
                float  vb = s_v[t * ESTR + 4];
                unsigned m = 0;
#pragma unroll
                for (int j = 0; j < LBL; j++) {
                    float y0 = va.x + Tl[0 * LBL + j];
                    float y1 = va.y + Tl[1 * LBL + j];
                    float y2 = va.z + Tl[2 * LBL + j];
                    float y3 = va.w + Tl[3 * LBL + j];
                    float y4 = vb   + Tl[4 * LBL + j];
                    float best = y0; unsigned idx = 0;
                    if (y1 > best) { best = y1; idx = 1; }
                    if (y2 > best) { best = y2; idx = 2; }
                    if (y3 > best) { best = y3; idx = 3; }
                    if (y4 > best) { best = y4; idx = 4; }
                    m |= idx << (4 * j);
                }
                s_F[t] = m;
            } else {
                s_F[t] = 0x43210u;   // identity map at t = SEQ-1
            }
        }
    }
    __syncthreads();

    // ------- single-warp suffix-scan backtrace (exact integer maps) -------
    if (warp == 0) {
        // lane l owns t in [16l, 16l+16)
        unsigned m[16];
#pragma unroll
        for (int k = 0; k < 16; k++) m[k] = s_F[16 * lane + k];

        // chunk product C = m[0] o m[1] o ... o m[15]
        unsigned C = m[15];
#pragma unroll
        for (int k = 14; k >= 0; k--) C = compose_map(m[k], C);

        // Kogge-Stone inclusive suffix scan over lanes
#pragma unroll
        for (int d = 1; d < 32; d <<= 1) {
            unsigned o = __shfl_down_sync(0xffffffffu, C, d);
            if (lane + d < 32) C = compose_map(C, o);
        }
        // entry tag for this lane = Sigma_{l+1}(last)
        unsigned Snext = __shfl_down_sync(0xffffffffu, C, 1);
        if (lane == 31) Snext = 0x43210u;
        int x = apply_map(Snext, s_last);
#pragma unroll
        for (int k = 15; k >= 0; k--) {
            x = apply_map(m[k], x);
            s_path[16 * lane + k] = (unsigned char)x;
        }
    } else if (warp == 1) {
        // warp-parallel deterministic loss reduction (last block only)
        if (s_islast) {
            float a = g_res[lane] + g_res[lane + 32];
#pragma unroll
            for (int off = 16; off; off >>= 1)
                a += __shfl_down_sync(0xffffffffu, a, off);
            if (lane == 0) {
                d_out[0] = -a / (float)(BATCH * SEQ);
                g_cnt = 0;  // reset for next graph replay
            }
        }
    }
    __syncthreads();

    // write decoded paths (float, coalesced)
    float* out_paths = d_out + 1;
    for (int t = tid; t < SEQ; t += 320)
        out_paths[(size_t)b * SEQ + t] = (float)s_path[t];
}

// ---------------------------------------------------------------------------
extern "C" void kernel_launch(void* const* d_in, const int* in_sizes, int n_in,
                              void* d_out, int out_size)
{
    const float* feats       = (const float*)d_in[0];  // [B,S,H]
    const int*   labels      = (const int*)  d_in[1];  // [B,S]
    // d_in[2] = mask: all-ones by construction, ignored
    const float* W_tag       = (const float*)d_in[3];  // [H,L]
    const float* b_tag       = (const float*)d_in[4];  // [L]
    const float* start_trans = (const float*)d_in[5];  // [L]
    const float* end_trans   = (const float*)d_in[6];  // [L]
    const float* trans       = (const float*)d_in[7];  // [L,L]
    const float* weights     = (const float*)d_in[8];  // [L]

    float* out = (float*)d_out;  // [0] = loss, [1..B*S] = paths

    emis_kernel<<<(BATCH * SEQ) / 64, 256>>>(feats, W_tag, b_tag);
    crf_kernel<<<BATCH, 320>>>(labels, start_trans, end_trans, trans, weights, out);
}